// round 8
// baseline (speedup 1.0000x reference)
#include <cuda_runtime.h>
#include <cuda_fp16.h>
#include <cstdint>

#define NN   100000
#define EE   3200000
#define FH   256
#define FIN  512
#define FOUT 64
#define HOPS 10
#define FR   64            // rows per fused-hop CTA

// ---------------- scratch (device globals) ----------------------------------
__device__ __half g_x16 [(size_t)NN * FIN];
__device__ __half g_x016[(size_t)NN * FH];
__device__ __half g_h16 [(size_t)NN * FH];
__device__ __half g_g16 [(size_t)NN * FH];   // second h buffer (ping-pong)
__device__ __half g_W1t [(size_t)FIN * FH];
__device__ __half g_W3p [(size_t)FH * FH];   // (W3 + I)^T, [n][k]
__device__ __half g_W2t [(size_t)FH * FOUT];
__device__ int    g_rowstart[NN + 1];
__device__ int    g_cnt[NN];
__device__ int2   g_epack[EE];

// ---------------- conversions ------------------------------------------------
__global__ void x2h_kernel(const float* __restrict__ x) {
    size_t i = (size_t)blockIdx.x * blockDim.x + threadIdx.x;
    if (i >= (size_t)NN * FIN / 8) return;
    float4 a = __ldg(((const float4*)x) + 2 * i);
    float4 b = __ldg(((const float4*)x) + 2 * i + 1);
    uint4 o;
    ((__half2*)&o)[0] = __floats2half2_rn(a.x, a.y);
    ((__half2*)&o)[1] = __floats2half2_rn(a.z, a.w);
    ((__half2*)&o)[2] = __floats2half2_rn(b.x, b.y);
    ((__half2*)&o)[3] = __floats2half2_rn(b.z, b.w);
    ((uint4*)g_x16)[i] = o;
}

__global__ void wt_kernel(const float* __restrict__ W, __half* __restrict__ Bt,
                          int K, int Nc, int addI) {
    int i = blockIdx.x * blockDim.x + threadIdx.x;
    if (i >= K * Nc) return;
    int n = i / K, k = i % K;
    float v = __ldg(&W[(size_t)k * Nc + n]);
    if (addI && k == n) v += 1.0f;
    Bt[i] = __float2half_rn(v);
}

// ---------------- CSR build --------------------------------------------------
__global__ void zero_cnt_kernel() {
    int i = blockIdx.x * blockDim.x + threadIdx.x;
    if (i < NN) g_cnt[i] = 0;
}

__global__ void hist_kernel(const int* __restrict__ erow) {
    int e = blockIdx.x * blockDim.x + threadIdx.x;
    if (e < EE) atomicAdd(&g_cnt[erow[e]], 1);
}

// exclusive scan; seeds g_cnt with offsets (scatter cursor)
__global__ void scan_kernel() {
    __shared__ int wsum[32];
    __shared__ int carry_s;
    int t = threadIdx.x, lane = t & 31, w = t >> 5;
    if (t == 0) carry_s = 0;
    __syncthreads();
    for (int base = 0; base < NN; base += 1024) {
        int i = base + t;
        int v = (i < NN) ? g_cnt[i] : 0;
        int s = v;
        #pragma unroll
        for (int off = 1; off < 32; off <<= 1) {
            int u = __shfl_up_sync(0xffffffff, s, off);
            if (lane >= off) s += u;
        }
        if (lane == 31) wsum[w] = s;
        __syncthreads();
        if (w == 0) {
            int ws = wsum[lane];
            #pragma unroll
            for (int off = 1; off < 32; off <<= 1) {
                int u = __shfl_up_sync(0xffffffff, ws, off);
                if (lane >= off) ws += u;
            }
            wsum[lane] = ws;
        }
        __syncthreads();
        int wpre = (w == 0) ? 0 : wsum[w - 1];
        if (i < NN) {
            int rs = carry_s + wpre + s - v;
            g_rowstart[i] = rs;
            g_cnt[i] = rs;          // scatter cursor
        }
        __syncthreads();
        if (t == 1023) carry_s += wsum[31];
        __syncthreads();
    }
    if (threadIdx.x == 0) g_rowstart[NN] = carry_s;
}

__global__ void scatter_kernel(const int* __restrict__ erow,
                               const int* __restrict__ ecol,
                               const float* __restrict__ eval) {
    int e = blockIdx.x * blockDim.x + threadIdx.x;
    if (e < EE) {
        int p = atomicAdd(&g_cnt[erow[e]], 1);
        g_epack[p] = make_int2(ecol[e], __float_as_int(eval[e]));
    }
}

// ---------------- mma helper --------------------------------------------------
__device__ __forceinline__ void mma_f16(float* d, const uint32_t* a, const uint32_t* b) {
    asm volatile(
        "mma.sync.aligned.m16n8k16.row.col.f32.f16.f16.f32 "
        "{%0,%1,%2,%3}, {%4,%5,%6,%7}, {%8,%9}, {%0,%1,%2,%3};\n"
        : "+f"(d[0]), "+f"(d[1]), "+f"(d[2]), "+f"(d[3])
        : "r"(a[0]), "r"(a[1]), "r"(a[2]), "r"(a[3]),
          "r"(b[0]), "r"(b[1]));
}

// ---------------- FUSED hop kernel --------------------------------------------
// Per CTA (256 thr): rows [b*64, b*64+64).
// Phase 1: t[r,:] = sum val*h[col,:] + A2[r]*x0[r,:]  -> smem fp16 tile At
// Phase 2: h_out[r,:] = relu(At @ (W3+I)^T + b3)      (64x256x256 HMMA)
#define AT_STRIDE 264
#define SM_AT_BYTES (FR * AT_STRIDE * 2)              // 33792
#define SM_BS_OFF   SM_AT_BYTES
#define SM_TOTAL    (SM_AT_BYTES + 256 * 40 * 2)      // 54272

__global__ __launch_bounds__(256, 2)
void hop_fused_kernel(const __half* __restrict__ hin,
                      const float* __restrict__ A2,
                      const __half* __restrict__ Bt,   // W3p [n][k]
                      const float* __restrict__ bias,
                      __half* __restrict__ hout) {
    extern __shared__ char smem[];
    __half (*At)[AT_STRIDE] = (__half (*)[AT_STRIDE])smem;
    __half (*Bs)[40]        = (__half (*)[40])(smem + SM_BS_OFF);

    const int tid  = threadIdx.x;
    const int wid  = tid >> 5;
    const int lane = tid & 31;
    const int m0   = blockIdx.x * FR;

    // ---------------- phase 1: gather ----------------
    #pragma unroll
    for (int i = 0; i < 8; i++) {
        int lrow = wid * 8 + i;          // 0..63
        int grow = m0 + lrow;
        float acc[8];
        #pragma unroll
        for (int q = 0; q < 8; q++) acc[q] = 0.f;
        if (grow < NN) {
            int s = g_rowstart[grow];
            int e = g_rowstart[grow + 1];
            #pragma unroll 4
            for (int p = s; p < e; ++p) {
                int2 ev = __ldg(&g_epack[p]);
                float v = __int_as_float(ev.y);
                uint4 raw = __ldg(((const uint4*)(hin + (size_t)ev.x * FH)) + lane);
                const __half2* hh = (const __half2*)&raw;
                #pragma unroll
                for (int q = 0; q < 4; q++) {
                    float2 f = __half22float2(hh[q]);
                    acc[2 * q]     += v * f.x;
                    acc[2 * q + 1] += v * f.y;
                }
            }
            float a = __ldg(&A2[grow]);
            uint4 xraw = __ldg(((const uint4*)(g_x016 + (size_t)grow * FH)) + lane);
            const __half2* xh = (const __half2*)&xraw;
            #pragma unroll
            for (int q = 0; q < 4; q++) {
                float2 f = __half22float2(xh[q]);
                acc[2 * q]     += a * f.x;
                acc[2 * q + 1] += a * f.y;
            }
        }
        uint4 o;
        #pragma unroll
        for (int q = 0; q < 4; q++)
            ((__half2*)&o)[q] = __floats2half2_rn(acc[2 * q], acc[2 * q + 1]);
        *(uint4*)&At[lrow][lane * 8] = o;
    }
    __syncthreads();

    // ---------------- phase 2: GEMM 64x256x256 ----------------
    const int gid = lane >> 2;
    const int tig = lane & 3;
    const int wm  = wid & 1;      // rows wm*32
    const int wn  = wid >> 1;     // cols wn*64

    float acc[2][8][4];
    #pragma unroll
    for (int i = 0; i < 2; i++)
        #pragma unroll
        for (int j = 0; j < 8; j++)
            #pragma unroll
            for (int q = 0; q < 4; q++) acc[i][j][q] = 0.f;

    for (int k0 = 0; k0 < FH; k0 += 32) {
        // load B tile: 256 n-rows x 32 k  (1024 uint4, 4/thread)
        #pragma unroll
        for (int i = 0; i < 4; i++) {
            int id = tid + i * 256;
            int r  = id >> 2;           // 0..255
            int g  = id & 3;
            *(uint4*)&Bs[r][g * 8] =
                *(const uint4*)(Bt + (size_t)r * FH + k0 + g * 8);
        }
        __syncthreads();

        #pragma unroll
        for (int kk = 0; kk < 32; kk += 16) {
            uint32_t afr[2][4];
            #pragma unroll
            for (int mt = 0; mt < 2; mt++) {
                int r = wm * 32 + mt * 16 + gid;
                afr[mt][0] = *(const uint32_t*)&At[r    ][k0 + kk + tig * 2];
                afr[mt][1] = *(const uint32_t*)&At[r + 8][k0 + kk + tig * 2];
                afr[mt][2] = *(const uint32_t*)&At[r    ][k0 + kk + tig * 2 + 8];
                afr[mt][3] = *(const uint32_t*)&At[r + 8][k0 + kk + tig * 2 + 8];
            }
            uint32_t bfr[8][2];
            #pragma unroll
            for (int nt = 0; nt < 8; nt++) {
                int cc = wn * 64 + nt * 8 + gid;
                bfr[nt][0] = *(const uint32_t*)&Bs[cc][kk + tig * 2];
                bfr[nt][1] = *(const uint32_t*)&Bs[cc][kk + tig * 2 + 8];
            }
            #pragma unroll
            for (int mt = 0; mt < 2; mt++)
                #pragma unroll
                for (int nt = 0; nt < 8; nt++)
                    mma_f16(acc[mt][nt], afr[mt], bfr[nt]);
        }
        __syncthreads();
    }

    // epilogue: bias + relu -> fp16
    #pragma unroll
    for (int mt = 0; mt < 2; mt++) {
        #pragma unroll
        for (int hm = 0; hm < 2; hm++) {
            int r = m0 + wm * 32 + mt * 16 + hm * 8 + gid;
            if (r >= NN) continue;
            #pragma unroll
            for (int nt = 0; nt < 8; nt++) {
                int c = wn * 64 + nt * 8 + tig * 2;
                float v0 = fmaxf(acc[mt][nt][hm * 2]     + __ldg(&bias[c]),     0.f);
                float v1 = fmaxf(acc[mt][nt][hm * 2 + 1] + __ldg(&bias[c + 1]), 0.f);
                *(__half2*)(hout + (size_t)r * FH + c) = __floats2half2_rn(v0, v1);
            }
        }
    }
}

// ---------------- dense GEMM (first + final layers, R4-proven) ---------------
// MODE 0: relu(acc+bias) -> fp16 O1 AND O2 ; MODE 2: acc+bias -> fp32 OF
template <int MODE>
__global__ __launch_bounds__(256, 2)
void gemm_f16_kernel(const __half* __restrict__ A, const __half* __restrict__ Bt,
                     const float* __restrict__ bias, float* __restrict__ OF,
                     __half* __restrict__ O1, __half* __restrict__ O2,
                     int M, int K, int Nc) {
    __shared__ __half As[128][40];
    __shared__ __half Bs[128][40];

    const int tid = threadIdx.x;
    const int wid = tid >> 5;
    const int lane = tid & 31;
    const int gid = lane >> 2;
    const int tig = lane & 3;
    const int wm = wid & 3;
    const int wn = wid >> 2;
    const int m0 = blockIdx.y * 128;
    const int n0 = blockIdx.x * 128;

    float acc[2][8][4];
    #pragma unroll
    for (int i = 0; i < 2; i++)
        #pragma unroll
        for (int j = 0; j < 8; j++)
            #pragma unroll
            for (int q = 0; q < 4; q++) acc[i][j][q] = 0.f;

    for (int k0 = 0; k0 < K; k0 += 32) {
        #pragma unroll
        for (int i = 0; i < 2; i++) {
            int id = tid + i * 256;
            int r  = id >> 2;
            int g  = id & 3;
            int gm = m0 + r;
            uint4 av = make_uint4(0u, 0u, 0u, 0u);
            if (gm < M)
                av = *(const uint4*)(A + (size_t)gm * K + k0 + g * 8);
            *(uint4*)&As[r][g * 8] = av;
        }
        #pragma unroll
        for (int i = 0; i < 2; i++) {
            int id = tid + i * 256;
            int r  = id >> 2;
            int g  = id & 3;
            int gn = n0 + r;
            uint4 bv = make_uint4(0u, 0u, 0u, 0u);
            if (gn < Nc)
                bv = *(const uint4*)(Bt + (size_t)gn * K + k0 + g * 8);
            *(uint4*)&Bs[r][g * 8] = bv;
        }
        __syncthreads();

        #pragma unroll
        for (int kk = 0; kk < 32; kk += 16) {
            uint32_t afr[2][4];
            #pragma unroll
            for (int mt = 0; mt < 2; mt++) {
                int r = wm * 32 + mt * 16 + gid;
                afr[mt][0] = *(const uint32_t*)&As[r    ][kk + tig * 2];
                afr[mt][1] = *(const uint32_t*)&As[r + 8][kk + tig * 2];
                afr[mt][2] = *(const uint32_t*)&As[r    ][kk + tig * 2 + 8];
                afr[mt][3] = *(const uint32_t*)&As[r + 8][kk + tig * 2 + 8];
            }
            uint32_t bfr[8][2];
            #pragma unroll
            for (int nt = 0; nt < 8; nt++) {
                int cc = wn * 64 + nt * 8 + gid;
                bfr[nt][0] = *(const uint32_t*)&Bs[cc][kk + tig * 2];
                bfr[nt][1] = *(const uint32_t*)&Bs[cc][kk + tig * 2 + 8];
            }
            #pragma unroll
            for (int mt = 0; mt < 2; mt++)
                #pragma unroll
                for (int nt = 0; nt < 8; nt++)
                    mma_f16(acc[mt][nt], afr[mt], bfr[nt]);
        }
        __syncthreads();
    }

    #pragma unroll
    for (int mt = 0; mt < 2; mt++) {
        #pragma unroll
        for (int hm = 0; hm < 2; hm++) {
            int r = m0 + wm * 32 + mt * 16 + hm * 8 + gid;
            if (r >= M) continue;
            #pragma unroll
            for (int nt = 0; nt < 8; nt++) {
                int c = n0 + wn * 64 + nt * 8 + tig * 2;
                if (c >= Nc) continue;
                float v0 = acc[mt][nt][hm * 2]     + __ldg(&bias[c]);
                float v1 = acc[mt][nt][hm * 2 + 1] + __ldg(&bias[c + 1]);
                if (MODE != 2) {
                    v0 = fmaxf(v0, 0.f); v1 = fmaxf(v1, 0.f);
                    __half2 hv = __floats2half2_rn(v0, v1);
                    *(__half2*)(O1 + (size_t)r * Nc + c) = hv;
                    if (MODE == 0)
                        *(__half2*)(O2 + (size_t)r * Nc + c) = hv;
                } else {
                    float* op = OF + (size_t)r * Nc + c;
                    op[0] = v0; op[1] = v1;
                }
            }
        }
    }
}

// ---------------- launch ------------------------------------------------------
extern "C" void kernel_launch(void* const* d_in, const int* in_sizes, int n_in,
                              void* d_out, int out_size) {
    const float* x    = (const float*)d_in[0];
    const int*   erow = (const int*)  d_in[1];
    const int*   ecol = (const int*)  d_in[2];
    const float* eval = (const float*)d_in[3];
    const float* A2   = (const float*)d_in[4];
    const float* W1   = (const float*)d_in[5];
    const float* b1   = (const float*)d_in[6];
    const float* W3   = (const float*)d_in[7];
    const float* b3   = (const float*)d_in[8];
    const float* W2   = (const float*)d_in[9];
    const float* b2   = (const float*)d_in[10];
    float* out = (float*)d_out;

    __half *px16, *px016, *ph16, *pg16, *pW1t, *pW3p, *pW2t;
    cudaGetSymbolAddress((void**)&px16,  g_x16);
    cudaGetSymbolAddress((void**)&px016, g_x016);
    cudaGetSymbolAddress((void**)&ph16,  g_h16);
    cudaGetSymbolAddress((void**)&pg16,  g_g16);
    cudaGetSymbolAddress((void**)&pW1t,  g_W1t);
    cudaGetSymbolAddress((void**)&pW3p,  g_W3p);
    cudaGetSymbolAddress((void**)&pW2t,  g_W2t);

    cudaFuncSetAttribute(hop_fused_kernel,
                         cudaFuncAttributeMaxDynamicSharedMemorySize, SM_TOTAL);

    // ---- conversions ----
    x2h_kernel<<<(int)(((size_t)NN * FIN / 8 + 255) / 256), 256>>>(x);
    wt_kernel<<<(FIN * FH + 255) / 256, 256>>>(W1, pW1t, FIN, FH, 0);
    wt_kernel<<<(FH * FH + 255) / 256, 256>>>(W3, pW3p, FH, FH, 1);
    wt_kernel<<<(FH * FOUT + 255) / 256, 256>>>(W2, pW2t, FH, FOUT, 0);

    // ---- CSR build ----
    zero_cnt_kernel<<<(NN + 255) / 256, 256>>>();
    hist_kernel<<<(EE + 255) / 256, 256>>>(erow);
    scan_kernel<<<1, 1024>>>();
    scatter_kernel<<<(EE + 255) / 256, 256>>>(erow, ecol, eval);

    // ---- x0 = relu(x @ W1 + b1) -> h16 and x016 ----
    dim3 grid1((FH + 127) / 128, (NN + 127) / 128);
    gemm_f16_kernel<0><<<grid1, 256>>>(px16, pW1t, b1, nullptr, ph16, px016,
                                       NN, FIN, FH);

    // ---- 10 fused hops (ping-pong h buffers) ----
    int hop_grid = (NN + FR - 1) / FR;
    __half* hcur = ph16;
    __half* hnxt = pg16;
    for (int i = 0; i < HOPS; i++) {
        hop_fused_kernel<<<hop_grid, 256, SM_TOTAL>>>(hcur, A2, pW3p, b3, hnxt);
        __half* t = hcur; hcur = hnxt; hnxt = t;
    }

    // ---- out = h @ W2 + b2 ----
    dim3 grid2((FOUT + 127) / 128, (NN + 127) / 128);
    gemm_f16_kernel<2><<<grid2, 256>>>(hcur, pW2t, b2, out, nullptr,
                                       nullptr, NN, FH, FOUT);
}

// round 9
// speedup vs baseline: 1.4109x; 1.4109x over previous
#include <cuda_runtime.h>
#include <cuda_fp16.h>
#include <cstdint>

#define NN   100000
#define EE   3200000
#define FH   256
#define FIN  512
#define FOUT 64
#define HOPS 10

// ---------------- scratch (device globals) ----------------------------------
__device__ __half g_x16 [(size_t)NN * FIN];  // x fp16; later reused for A2*x0
__device__ __half g_x016[(size_t)NN * FH];   // x0 fp16
__device__ __half g_h16 [(size_t)NN * FH];   // h (in-place across hops)
__device__ __half g_t16 [(size_t)NN * FH];   // spmm output
__device__ __half g_c016[(size_t)NN * FH];   // C0 = (A2*x0)@(W3+I)+b3
__device__ __half g_W1t [(size_t)FIN * FH];
__device__ __half g_W3p [(size_t)FH * FH];   // (W3 + I)^T, [n][k]
__device__ __half g_W2t [(size_t)FH * FOUT];
__device__ int    g_rowstart[NN + 1];
__device__ int    g_cnt[NN];
__device__ int2   g_epack[EE];

// ---------------- conversions ------------------------------------------------
__global__ void x2h_kernel(const float* __restrict__ x) {
    size_t i = (size_t)blockIdx.x * blockDim.x + threadIdx.x;
    if (i >= (size_t)NN * FIN / 8) return;
    float4 a = __ldg(((const float4*)x) + 2 * i);
    float4 b = __ldg(((const float4*)x) + 2 * i + 1);
    uint4 o;
    ((__half2*)&o)[0] = __floats2half2_rn(a.x, a.y);
    ((__half2*)&o)[1] = __floats2half2_rn(a.z, a.w);
    ((__half2*)&o)[2] = __floats2half2_rn(b.x, b.y);
    ((__half2*)&o)[3] = __floats2half2_rn(b.z, b.w);
    ((uint4*)g_x16)[i] = o;
}

__global__ void wt_kernel(const float* __restrict__ W, __half* __restrict__ Bt,
                          int K, int Nc, int addI) {
    int i = blockIdx.x * blockDim.x + threadIdx.x;
    if (i >= K * Nc) return;
    int n = i / K, k = i % K;
    float v = __ldg(&W[(size_t)k * Nc + n]);
    if (addI && k == n) v += 1.0f;
    Bt[i] = __float2half_rn(v);
}

// ax16[row, :] = A2[row] * x016[row, :]   (written into g_x16, reused)
__global__ void ax_kernel(const float* __restrict__ A2) {
    int row  = blockIdx.x * 8 + (threadIdx.x >> 5);
    int lane = threadIdx.x & 31;
    if (row >= NN) return;
    float a = __ldg(&A2[row]);
    uint4 raw = __ldg(((const uint4*)(g_x016 + (size_t)row * FH)) + lane);
    const __half2* xh = (const __half2*)&raw;
    uint4 o;
    #pragma unroll
    for (int q = 0; q < 4; q++) {
        float2 f = __half22float2(xh[q]);
        ((__half2*)&o)[q] = __floats2half2_rn(a * f.x, a * f.y);
    }
    ((uint4*)(g_x16 + (size_t)row * FH))[lane] = o;
}

// ---------------- CSR build --------------------------------------------------
__global__ void zero_cnt_kernel() {
    int i = blockIdx.x * blockDim.x + threadIdx.x;
    if (i < NN) g_cnt[i] = 0;
}

__global__ void hist_kernel(const int* __restrict__ erow) {
    int e = blockIdx.x * blockDim.x + threadIdx.x;
    if (e < EE) atomicAdd(&g_cnt[erow[e]], 1);
}

// exclusive scan; seeds g_cnt with offsets (scatter cursor)
__global__ void scan_kernel() {
    __shared__ int wsum[32];
    __shared__ int carry_s;
    int t = threadIdx.x, lane = t & 31, w = t >> 5;
    if (t == 0) carry_s = 0;
    __syncthreads();
    for (int base = 0; base < NN; base += 1024) {
        int i = base + t;
        int v = (i < NN) ? g_cnt[i] : 0;
        int s = v;
        #pragma unroll
        for (int off = 1; off < 32; off <<= 1) {
            int u = __shfl_up_sync(0xffffffff, s, off);
            if (lane >= off) s += u;
        }
        if (lane == 31) wsum[w] = s;
        __syncthreads();
        if (w == 0) {
            int ws = wsum[lane];
            #pragma unroll
            for (int off = 1; off < 32; off <<= 1) {
                int u = __shfl_up_sync(0xffffffff, ws, off);
                if (lane >= off) ws += u;
            }
            wsum[lane] = ws;
        }
        __syncthreads();
        int wpre = (w == 0) ? 0 : wsum[w - 1];
        if (i < NN) {
            int rs = carry_s + wpre + s - v;
            g_rowstart[i] = rs;
            g_cnt[i] = rs;
        }
        __syncthreads();
        if (t == 1023) carry_s += wsum[31];
        __syncthreads();
    }
    if (threadIdx.x == 0) g_rowstart[NN] = carry_s;
}

__global__ void scatter_kernel(const int* __restrict__ erow,
                               const int* __restrict__ ecol,
                               const float* __restrict__ eval) {
    int e = blockIdx.x * blockDim.x + threadIdx.x;
    if (e < EE) {
        int p = atomicAdd(&g_cnt[erow[e]], 1);
        g_epack[p] = make_int2(ecol[e], __float_as_int(eval[e]));
    }
}

// ---------------- SPMM: t16[row,:] = sum val*h16[col,:]  (pure gather) -------
__global__ void spmm_kernel(const __half* __restrict__ h) {
    int row  = blockIdx.x * 8 + (threadIdx.x >> 5);
    int lane = threadIdx.x & 31;
    if (row >= NN) return;
    int s = g_rowstart[row];
    int e = g_rowstart[row + 1];
    float acc[8];
    #pragma unroll
    for (int q = 0; q < 8; q++) acc[q] = 0.f;

    #pragma unroll 4
    for (int p = s; p < e; ++p) {
        int2 ev = __ldcs(&g_epack[p]);                  // streaming
        float v = __int_as_float(ev.y);
        uint4 raw = __ldg(((const uint4*)(h + (size_t)ev.x * FH)) + lane);
        const __half2* hh = (const __half2*)&raw;
        #pragma unroll
        for (int q = 0; q < 4; q++) {
            float2 f = __half22float2(hh[q]);
            acc[2 * q]     += v * f.x;
            acc[2 * q + 1] += v * f.y;
        }
    }
    uint4 o;
    #pragma unroll
    for (int q = 0; q < 4; q++)
        ((__half2*)&o)[q] = __floats2half2_rn(acc[2 * q], acc[2 * q + 1]);
    __stcs(((uint4*)(g_t16 + (size_t)row * FH)) + lane, o);   // evict-first
}

// ---------------- fp16 mma.sync GEMM ------------------------------------------
// MODE 0: relu(acc+bias) -> fp16 O1 AND O2            (first layer)
// MODE 2: acc+bias       -> fp32 OF                   (final layer)
// MODE 3: acc+bias       -> fp16 O1, no relu          (C0 build)
// MODE 4: relu(acc+C16)  -> fp16 O1, A streamed       (hop layer)
__device__ __forceinline__ void mma_f16(float* d, const uint32_t* a, const uint32_t* b) {
    asm volatile(
        "mma.sync.aligned.m16n8k16.row.col.f32.f16.f16.f32 "
        "{%0,%1,%2,%3}, {%4,%5,%6,%7}, {%8,%9}, {%0,%1,%2,%3};\n"
        : "+f"(d[0]), "+f"(d[1]), "+f"(d[2]), "+f"(d[3])
        : "r"(a[0]), "r"(a[1]), "r"(a[2]), "r"(a[3]),
          "r"(b[0]), "r"(b[1]));
}

template <int MODE>
__global__ __launch_bounds__(256, 2)
void gemm_f16_kernel(const __half* __restrict__ A, const __half* __restrict__ Bt,
                     const float* __restrict__ bias, const __half* __restrict__ C16,
                     float* __restrict__ OF, __half* __restrict__ O1,
                     __half* __restrict__ O2, int M, int K, int Nc) {
    __shared__ __half As[128][40];
    __shared__ __half Bs[128][40];

    const int tid = threadIdx.x;
    const int wid = tid >> 5;
    const int lane = tid & 31;
    const int gid = lane >> 2;
    const int tig = lane & 3;
    const int wm = wid & 3;
    const int wn = wid >> 2;
    const int m0 = blockIdx.y * 128;
    const int n0 = blockIdx.x * 128;

    float acc[2][8][4];
    #pragma unroll
    for (int i = 0; i < 2; i++)
        #pragma unroll
        for (int j = 0; j < 8; j++)
            #pragma unroll
            for (int q = 0; q < 4; q++) acc[i][j][q] = 0.f;

    for (int k0 = 0; k0 < K; k0 += 32) {
        #pragma unroll
        for (int i = 0; i < 2; i++) {
            int id = tid + i * 256;
            int r  = id >> 2;
            int g  = id & 3;
            int gm = m0 + r;
            uint4 av = make_uint4(0u, 0u, 0u, 0u);
            if (gm < M) {
                const uint4* p = (const uint4*)(A + (size_t)gm * K + k0 + g * 8);
                av = (MODE == 4) ? __ldcs(p) : __ldg(p);
            }
            *(uint4*)&As[r][g * 8] = av;
        }
        #pragma unroll
        for (int i = 0; i < 2; i++) {
            int id = tid + i * 256;
            int r  = id >> 2;
            int g  = id & 3;
            int gn = n0 + r;
            uint4 bv = make_uint4(0u, 0u, 0u, 0u);
            if (gn < Nc)
                bv = __ldg((const uint4*)(Bt + (size_t)gn * K + k0 + g * 8));
            *(uint4*)&Bs[r][g * 8] = bv;
        }
        __syncthreads();

        #pragma unroll
        for (int kk = 0; kk < 32; kk += 16) {
            uint32_t afr[2][4];
            #pragma unroll
            for (int mt = 0; mt < 2; mt++) {
                int r = wm * 32 + mt * 16 + gid;
                afr[mt][0] = *(const uint32_t*)&As[r    ][kk + tig * 2];
                afr[mt][1] = *(const uint32_t*)&As[r + 8][kk + tig * 2];
                afr[mt][2] = *(const uint32_t*)&As[r    ][kk + tig * 2 + 8];
                afr[mt][3] = *(const uint32_t*)&As[r + 8][kk + tig * 2 + 8];
            }
            uint32_t bfr[8][2];
            #pragma unroll
            for (int nt = 0; nt < 8; nt++) {
                int cc = wn * 64 + nt * 8 + gid;
                bfr[nt][0] = *(const uint32_t*)&Bs[cc][kk + tig * 2];
                bfr[nt][1] = *(const uint32_t*)&Bs[cc][kk + tig * 2 + 8];
            }
            #pragma unroll
            for (int mt = 0; mt < 2; mt++)
                #pragma unroll
                for (int nt = 0; nt < 8; nt++)
                    mma_f16(acc[mt][nt], afr[mt], bfr[nt]);
        }
        __syncthreads();
    }

    #pragma unroll
    for (int mt = 0; mt < 2; mt++) {
        #pragma unroll
        for (int hm = 0; hm < 2; hm++) {
            int r = m0 + wm * 32 + mt * 16 + hm * 8 + gid;
            if (r >= M) continue;
            #pragma unroll
            for (int nt = 0; nt < 8; nt++) {
                int c = n0 + wn * 64 + nt * 8 + tig * 2;
                if (c >= Nc) continue;
                float v0 = acc[mt][nt][hm * 2];
                float v1 = acc[mt][nt][hm * 2 + 1];
                if (MODE == 4) {
                    __half2 cv = __ldcs((const __half2*)(C16 + (size_t)r * Nc + c));
                    float2 cf = __half22float2(cv);
                    v0 += cf.x; v1 += cf.y;
                } else {
                    v0 += __ldg(&bias[c]);
                    v1 += __ldg(&bias[c + 1]);
                }
                if (MODE == 0 || MODE == 4) { v0 = fmaxf(v0, 0.f); v1 = fmaxf(v1, 0.f); }
                if (MODE == 2) {
                    float* op = OF + (size_t)r * Nc + c;
                    op[0] = v0; op[1] = v1;
                } else {
                    __half2 hv = __floats2half2_rn(v0, v1);
                    *(__half2*)(O1 + (size_t)r * Nc + c) = hv;
                    if (MODE == 0)
                        *(__half2*)(O2 + (size_t)r * Nc + c) = hv;
                }
            }
        }
    }
}

// ---------------- launch ------------------------------------------------------
extern "C" void kernel_launch(void* const* d_in, const int* in_sizes, int n_in,
                              void* d_out, int out_size) {
    const float* x    = (const float*)d_in[0];
    const int*   erow = (const int*)  d_in[1];
    const int*   ecol = (const int*)  d_in[2];
    const float* eval = (const float*)d_in[3];
    const float* A2   = (const float*)d_in[4];
    const float* W1   = (const float*)d_in[5];
    const float* b1   = (const float*)d_in[6];
    const float* W3   = (const float*)d_in[7];
    const float* b3   = (const float*)d_in[8];
    const float* W2   = (const float*)d_in[9];
    const float* b2   = (const float*)d_in[10];
    float* out = (float*)d_out;

    __half *px16, *px016, *ph16, *pt16, *pc016, *pW1t, *pW3p, *pW2t;
    cudaGetSymbolAddress((void**)&px16,  g_x16);
    cudaGetSymbolAddress((void**)&px016, g_x016);
    cudaGetSymbolAddress((void**)&ph16,  g_h16);
    cudaGetSymbolAddress((void**)&pt16,  g_t16);
    cudaGetSymbolAddress((void**)&pc016, g_c016);
    cudaGetSymbolAddress((void**)&pW1t,  g_W1t);
    cudaGetSymbolAddress((void**)&pW3p,  g_W3p);
    cudaGetSymbolAddress((void**)&pW2t,  g_W2t);

    // ---- conversions ----
    x2h_kernel<<<(int)(((size_t)NN * FIN / 8 + 255) / 256), 256>>>(x);
    wt_kernel<<<(FIN * FH + 255) / 256, 256>>>(W1, pW1t, FIN, FH, 0);
    wt_kernel<<<(FH * FH + 255) / 256, 256>>>(W3, pW3p, FH, FH, 1);
    wt_kernel<<<(FH * FOUT + 255) / 256, 256>>>(W2, pW2t, FH, FOUT, 0);

    // ---- CSR build ----
    zero_cnt_kernel<<<(NN + 255) / 256, 256>>>();
    hist_kernel<<<(EE + 255) / 256, 256>>>(erow);
    scan_kernel<<<1, 1024>>>();
    scatter_kernel<<<(EE + 255) / 256, 256>>>(erow, ecol, eval);

    // ---- x0 = relu(x @ W1 + b1) -> h16 and x016 ----
    dim3 grid1((FH + 127) / 128, (NN + 127) / 128);
    gemm_f16_kernel<0><<<grid1, 256>>>(px16, pW1t, b1, nullptr, nullptr,
                                       ph16, px016, NN, FIN, FH);

    // ---- C0 = (A2*x0) @ (W3+I) + b3  (hop-invariant) ----
    ax_kernel<<<(NN + 7) / 8, 256>>>(A2);     // g_x16 := A2 * x016
    dim3 grid3((FH + 127) / 128, (NN + 127) / 128);
    gemm_f16_kernel<3><<<grid3, 256>>>(px16, pW3p, b3, nullptr, nullptr,
                                       pc016, nullptr, NN, FH, FH);

    // ---- 10 hops, in-place h: t = S*h ; h = relu(t @ (W3+I) + C0) ----
    for (int i = 0; i < HOPS; i++) {
        spmm_kernel<<<(NN + 7) / 8, 256>>>(ph16);
        gemm_f16_kernel<4><<<grid3, 256>>>(pt16, pW3p, nullptr, pc016, nullptr,
                                           ph16, nullptr, NN, FH, FH);
    }

    // ---- out = h @ W2 + b2 ----
    dim3 grid2((FOUT + 127) / 128, (NN + 127) / 128);
    gemm_f16_kernel<2><<<grid2, 256>>>(ph16, pW2t, b2, nullptr, out,
                                       nullptr, nullptr, NN, FH, FOUT);
}